// round 14
// baseline (speedup 1.0000x reference)
#include <cuda_runtime.h>
#include <cfloat>
#include <climits>

#define VOCAB 30522
#define CAND_CAP (1 << 20)
#define OVF_CAP  (1 << 18)
#define TOPK 10
#define NB1 296
#define STAGE_CAP 2048

// ---- device scratch (BSS zero-init; every launch restores the invariant) ----
__device__ float g_scores[500000];
__device__ int   g_cand_doc[CAND_CAP];
__device__ int   g_ncand;          // reset by topk last block
__device__ int   g_ovf_pos[OVF_CAP];
__device__ float g_ovf_val[OVF_CAP];
__device__ int   g_novf;           // reset by topk last block
__device__ int   g_done;           // score CTA ticket, reset by topk last block
__device__ int   g_tk_done;        // topk block ticket, reset by topk last block
__device__ float g_blk_v[NB1 * TOPK];
__device__ int   g_blk_i[NB1 * TOPK];

// ---------------------------------------------------------------------------
// score_fused: stream nnz (4x-batched int4 -> DRAM MLP>=4). KEY SCHEDULING
// RULE: all 16 qtab LDS are issued back-to-back into registers BEFORE any
// conditional emit -- the emit path stores to shared (sc_pos/sc_val), and a
// conditional STS between LDS ops creates a false alias dependency that
// serializes the crossbar. Loads first = fully pipelined LDS.
// CTA-local hit staging + per-CTA resolve; t0-only cumulative fences.
// ---------------------------------------------------------------------------
__global__ void __launch_bounds__(1024, 1)
score_kernel(const int* __restrict__ qidx, const float* __restrict__ qval, int qn,
             const int* __restrict__ indice, const float* __restrict__ values,
             const int* __restrict__ crow, int n_docs, int nnz)
{
    extern __shared__ float qtab[];   // VOCAB floats = 122088 B
    __shared__ int   sc_cnt;
    __shared__ int   sc_pos[STAGE_CAP];
    __shared__ float sc_val[STAGE_CAP];
    __shared__ int   cd_cnt;
    __shared__ int   cd_doc[STAGE_CAP];
    __shared__ int   cd_base, cd_flush;
    __shared__ int   s_last;

    for (int i = threadIdx.x; i < VOCAB; i += 1024) qtab[i] = 0.0f;
    if (threadIdx.x == 0) { sc_cnt = 0; cd_cnt = 0; }
    __syncthreads();
    if (threadIdx.x < qn) atomicAdd(&qtab[qidx[threadIdx.x]], qval[threadIdx.x]);
    __syncthreads();

    const int gtid = blockIdx.x * 1024 + threadIdx.x;
    const int gsz  = gridDim.x * 1024;
    const int total4 = nnz >> 2;
    const int4* __restrict__ ind4 = (const int4*)indice;

    // test-and-stage on a PRELOADED q value (no LDS inside)
    #define TESTQ(q, jj)                                                       \
        if ((q) != 0.0f) {                                                     \
            float v = (q) * __ldg(values + (jj));                              \
            int p = atomicAdd(&sc_cnt, 1);                                     \
            if (p < STAGE_CAP) { sc_pos[p] = (jj); sc_val[p] = v; }            \
            else {                                                             \
                int gp = atomicAdd(&g_novf, 1);                                \
                if (gp < OVF_CAP) {                                            \
                    g_ovf_pos[gp] = (jj); g_ovf_val[gp] = v;                   \
                }                                                              \
            }                                                                  \
        }

    int i = gtid;
    for (; i + 3 * gsz < total4; i += 4 * gsz) {
        int4 a = __ldcs(ind4 + i);
        int4 b = __ldcs(ind4 + i + gsz);
        int4 c = __ldcs(ind4 + i + 2 * gsz);
        int4 d = __ldcs(ind4 + i + 3 * gsz);

        // 16 independent LDS, no intervening stores -> pipelined crossbar
        float q00 = qtab[a.x], q01 = qtab[a.y], q02 = qtab[a.z], q03 = qtab[a.w];
        float q04 = qtab[b.x], q05 = qtab[b.y], q06 = qtab[b.z], q07 = qtab[b.w];
        float q08 = qtab[c.x], q09 = qtab[c.y], q10 = qtab[c.z], q11 = qtab[c.w];
        float q12 = qtab[d.x], q13 = qtab[d.y], q14 = qtab[d.z], q15 = qtab[d.w];

        int ja = i << 2, jb = (i + gsz) << 2, jc = (i + 2 * gsz) << 2, jd = (i + 3 * gsz) << 2;
        TESTQ(q00, ja)     TESTQ(q01, ja + 1) TESTQ(q02, ja + 2) TESTQ(q03, ja + 3)
        TESTQ(q04, jb)     TESTQ(q05, jb + 1) TESTQ(q06, jb + 2) TESTQ(q07, jb + 3)
        TESTQ(q08, jc)     TESTQ(q09, jc + 1) TESTQ(q10, jc + 2) TESTQ(q11, jc + 3)
        TESTQ(q12, jd)     TESTQ(q13, jd + 1) TESTQ(q14, jd + 2) TESTQ(q15, jd + 3)
    }
    for (; i < total4; i += gsz) {
        int4 a = __ldcs(ind4 + i);
        float q0 = qtab[a.x], q1 = qtab[a.y], q2 = qtab[a.z], q3 = qtab[a.w];
        int j = i << 2;
        TESTQ(q0, j) TESTQ(q1, j + 1) TESTQ(q2, j + 2) TESTQ(q3, j + 3)
    }
    int jt = (total4 << 2) + gtid;
    if (jt < nnz) {
        float q = qtab[indice[jt]];
        TESTQ(q, jt)
    }
    #undef TESTQ

    // ---- per-CTA resolve of staged hits (parallel binary searches) ----
    __syncthreads();
    int nh = sc_cnt; if (nh > STAGE_CAP) nh = STAGE_CAP;
    for (int t = threadIdx.x; t < nh; t += 1024) {
        int j = sc_pos[t];
        int lo = 0, hi = n_docs;
        while (lo < hi) {
            int mid = (lo + hi + 1) >> 1;
            if (crow[mid] <= j) lo = mid; else hi = mid - 1;
        }
        float old = atomicAdd(&g_scores[lo], sc_val[t]);
        if (old == 0.0f) {
            int p = atomicAdd(&cd_cnt, 1);
            if (p < STAGE_CAP) cd_doc[p] = lo;
            else {
                int gp = atomicAdd(&g_ncand, 1);
                if (gp < CAND_CAP) g_cand_doc[gp] = lo;
            }
        }
    }

    // ---- flush candidates: ONE global atomic per CTA ----
    __syncthreads();
    if (threadIdx.x == 0) {
        int c = cd_cnt; if (c > STAGE_CAP) c = STAGE_CAP;
        int base = atomicAdd(&g_ncand, c);
        if (base + c > CAND_CAP) c = (base < CAND_CAP) ? (CAND_CAP - base) : 0;
        cd_base = base; cd_flush = c;
    }
    __syncthreads();
    for (int t = threadIdx.x; t < cd_flush; t += 1024)
        g_cand_doc[cd_base + t] = cd_doc[t];

    // ---- completion ticket: t0-only cumulative fence (release+acquire) ----
    __syncthreads();
    if (threadIdx.x == 0) {
        __threadfence();
        s_last = (atomicAdd(&g_done, 1) == gridDim.x - 1) ? 1 : 0;
        if (s_last) __threadfence();
    }
    __syncthreads();
    if (s_last) {
        int no = g_novf; if (no > OVF_CAP) no = OVF_CAP;
        for (int t = threadIdx.x; t < no; t += 1024) {
            int j = g_ovf_pos[t];
            int lo = 0, hi = n_docs;
            while (lo < hi) {
                int mid = (lo + hi + 1) >> 1;
                if (crow[mid] <= j) lo = mid; else hi = mid - 1;
            }
            float old = atomicAdd(&g_scores[lo], g_ovf_val[t]);
            if (old == 0.0f) {
                int gp = atomicAdd(&g_ncand, 1);
                if (gp < CAND_CAP) g_cand_doc[gp] = lo;
            }
        }
    }
}

// ---------------------------------------------------------------------------
// top-k helpers (static register indexing only)
// ---------------------------------------------------------------------------
__device__ __forceinline__ void insert10(float* lv, int* li, float s, int d) {
    if (s > lv[TOPK - 1] || (s == lv[TOPK - 1] && d < li[TOPK - 1])) {
        lv[TOPK - 1] = s; li[TOPK - 1] = d;
        #pragma unroll
        for (int k = TOPK - 1; k > 0; k--) {
            bool sw = (lv[k] > lv[k - 1]) ||
                      (lv[k] == lv[k - 1] && li[k] < li[k - 1]);
            if (sw) {
                float tv = lv[k]; lv[k] = lv[k - 1]; lv[k - 1] = tv;
                int   ti = li[k]; li[k] = li[k - 1]; li[k - 1] = ti;
            }
        }
    }
}

__device__ __forceinline__ void warp_merge10(float* lv, int* li,
                                             float* out_v, int* out_i) {
    int lane = threadIdx.x & 31;
    #pragma unroll
    for (int r = 0; r < TOPK; r++) {
        float bv = lv[0]; int bi = li[0]; int bl = lane;
        #pragma unroll
        for (int off = 16; off; off >>= 1) {
            float ov = __shfl_down_sync(0xffffffffu, bv, off);
            int   oi = __shfl_down_sync(0xffffffffu, bi, off);
            int   ol = __shfl_down_sync(0xffffffffu, bl, off);
            if (ov > bv || (ov == bv && oi < bi)) { bv = ov; bi = oi; bl = ol; }
        }
        bl = __shfl_sync(0xffffffffu, bl, 0);
        float wv = __shfl_sync(0xffffffffu, bv, 0);
        int   wi = __shfl_sync(0xffffffffu, bi, 0);
        if (lane == bl) {
            #pragma unroll
            for (int k = 0; k < TOPK - 1; k++) { lv[k] = lv[k + 1]; li[k] = li[k + 1]; }
            lv[TOPK - 1] = -FLT_MAX; li[TOPK - 1] = INT_MAX;
        }
        if (lane == 0) { out_v[r] = wv; out_i[r] = wi; }
    }
}

__device__ __forceinline__ void block_merge10(const float* sv, const int* si,
                                              int nwarp, float* out_v, int* out_i) {
    int lane = threadIdx.x & 31;
    float lv[TOPK]; int li[TOPK];
    #pragma unroll
    for (int k = 0; k < TOPK; k++) {
        if (lane < nwarp) { lv[k] = sv[lane * TOPK + k]; li[k] = si[lane * TOPK + k]; }
        else              { lv[k] = -FLT_MAX;            li[k] = INT_MAX;            }
    }
    warp_merge10(lv, li, out_v, out_i);
}

// ---------------------------------------------------------------------------
// top-k (single kernel): per-block candidate scan with fused cleanup, block
// winners to global; last-finishing block merges winners, writes output,
// resets counters. out layout: [TOPK values][TOPK indices-as-float]
// ---------------------------------------------------------------------------
__global__ void __launch_bounds__(256)
topk_kernel(float* __restrict__ out, int out_size) {
    __shared__ float sv[8 * TOPK];
    __shared__ int   si[8 * TOPK];
    __shared__ int   s_last;

    float lv[TOPK]; int li[TOPK];
    #pragma unroll
    for (int k = 0; k < TOPK; k++) { lv[k] = -FLT_MAX; li[k] = INT_MAX; }

    int nc = g_ncand;
    if (nc > CAND_CAP) nc = CAND_CAP;
    int gtid = blockIdx.x * blockDim.x + threadIdx.x;
    int gsz  = gridDim.x * blockDim.x;

    int t = gtid;
    for (; t + 3 * gsz < nc; t += 4 * gsz) {
        int d0 = g_cand_doc[t];
        int d1 = g_cand_doc[t + gsz];
        int d2 = g_cand_doc[t + 2 * gsz];
        int d3 = g_cand_doc[t + 3 * gsz];
        float s0 = g_scores[d0];
        float s1 = g_scores[d1];
        float s2 = g_scores[d2];
        float s3 = g_scores[d3];
        g_scores[d0] = 0.0f;
        g_scores[d1] = 0.0f;
        g_scores[d2] = 0.0f;
        g_scores[d3] = 0.0f;
        insert10(lv, li, s0, d0);
        insert10(lv, li, s1, d1);
        insert10(lv, li, s2, d2);
        insert10(lv, li, s3, d3);
    }
    for (; t < nc; t += gsz) {
        int d = g_cand_doc[t];
        float s = g_scores[d];
        g_scores[d] = 0.0f;
        insert10(lv, li, s, d);
    }

    int wid = threadIdx.x >> 5;
    warp_merge10(lv, li, sv + wid * TOPK, si + wid * TOPK);
    __syncthreads();
    if (wid == 0)
        block_merge10(sv, si, 8, g_blk_v + blockIdx.x * TOPK,
                      g_blk_i + blockIdx.x * TOPK);

    // ---- ticket: t0-only cumulative fence ----
    __syncthreads();
    if (threadIdx.x == 0) {
        __threadfence();
        s_last = (atomicAdd(&g_tk_done, 1) == gridDim.x - 1) ? 1 : 0;
        if (s_last) __threadfence();
    }
    __syncthreads();
    if (!s_last) return;

    const int NC = NB1 * TOPK;
    #pragma unroll
    for (int k = 0; k < TOPK; k++) { lv[k] = -FLT_MAX; li[k] = INT_MAX; }
    for (int p = threadIdx.x; p < NC; p += 256)
        insert10(lv, li, g_blk_v[p], g_blk_i[p]);

    __syncthreads();   // reuse sv/si
    warp_merge10(lv, li, sv + wid * TOPK, si + wid * TOPK);
    __syncthreads();
    __shared__ float fv[TOPK];
    __shared__ int   fi[TOPK];
    if (wid == 0) block_merge10(sv, si, 8, fv, fi);
    __syncthreads();

    if (threadIdx.x < TOPK) {
        int k = threadIdx.x;
        if (k < out_size) out[k] = fv[k];
        if (TOPK + k < out_size) out[TOPK + k] = (float)fi[k];
    }
    if (threadIdx.x == 0) {   // reset all counters for next graph replay
        g_ncand = 0;
        g_novf = 0;
        g_done = 0;
        g_tk_done = 0;
    }
}

// ---------------------------------------------------------------------------
// kernel_launch
// Inputs: q_indices(i32,32) q_values(f32,32) crow(i32,N+1) indice(i32,nnz)
//         values(f32,nnz) [top_k]
// ---------------------------------------------------------------------------
extern "C" void kernel_launch(void* const* d_in, const int* in_sizes, int n_in,
                              void* d_out, int out_size) {
    const int*   qidx   = (const int*)d_in[0];
    const float* qval   = (const float*)d_in[1];
    const int*   crow   = (const int*)d_in[2];
    const int*   indice = (const int*)d_in[3];
    const float* values = (const float*)d_in[4];

    int qn     = in_sizes[0];
    int n_docs = in_sizes[2] - 1;
    int nnz    = in_sizes[3];

    const int SMEM_Q = VOCAB * (int)sizeof(float);
    cudaFuncSetAttribute(score_kernel, cudaFuncAttributeMaxDynamicSharedMemorySize, SMEM_Q);

    score_kernel<<<148, 1024, SMEM_Q>>>(qidx, qval, qn, indice, values,
                                        crow, n_docs, nnz);
    topk_kernel<<<NB1, 256>>>((float*)d_out, out_size);
}

// round 15
// speedup vs baseline: 1.0408x; 1.0408x over previous
#include <cuda_runtime.h>
#include <cfloat>
#include <climits>

#define VOCAB 30522
#define CAND_CAP (1 << 20)
#define OVF_CAP  (1 << 18)
#define TOPK 10
#define NB1 296
#define STAGE_CAP 2048

// ---- device scratch (BSS zero-init; every launch restores the invariant) ----
__device__ float g_scores[500000];
__device__ int   g_cand_doc[CAND_CAP];
__device__ int   g_ncand;          // reset by topk last block
__device__ int   g_ovf_pos[OVF_CAP];
__device__ float g_ovf_val[OVF_CAP];
__device__ int   g_novf;           // reset by topk last block
__device__ int   g_done;           // score CTA ticket, reset by topk last block
__device__ int   g_tk_done;        // topk block ticket, reset by topk last block
__device__ float g_blk_v[NB1 * TOPK];
__device__ int   g_blk_i[NB1 * TOPK];

// ---------------------------------------------------------------------------
// score_fused: stream nnz (4x-batched int4 -> DRAM MLP>=4). LDS preloaded in
// GROUPS OF 4 (per int4): amortizes the 29-cyc LDS latency without blowing
// the 64-reg budget at 1024 threads (preload-16 and 8x-LDG both spilled).
// CTA-local hit staging + per-CTA resolve; t0-only cumulative fences.
// ---------------------------------------------------------------------------
__global__ void __launch_bounds__(1024, 1)
score_kernel(const int* __restrict__ qidx, const float* __restrict__ qval, int qn,
             const int* __restrict__ indice, const float* __restrict__ values,
             const int* __restrict__ crow, int n_docs, int nnz)
{
    extern __shared__ float qtab[];   // VOCAB floats = 122088 B
    __shared__ int   sc_cnt;
    __shared__ int   sc_pos[STAGE_CAP];
    __shared__ float sc_val[STAGE_CAP];
    __shared__ int   cd_cnt;
    __shared__ int   cd_doc[STAGE_CAP];
    __shared__ int   cd_base, cd_flush;
    __shared__ int   s_last;

    for (int i = threadIdx.x; i < VOCAB; i += 1024) qtab[i] = 0.0f;
    if (threadIdx.x == 0) { sc_cnt = 0; cd_cnt = 0; }
    __syncthreads();
    if (threadIdx.x < qn) atomicAdd(&qtab[qidx[threadIdx.x]], qval[threadIdx.x]);
    __syncthreads();

    const int gtid = blockIdx.x * 1024 + threadIdx.x;
    const int gsz  = gridDim.x * 1024;
    const int total4 = nnz >> 2;
    const int4* __restrict__ ind4 = (const int4*)indice;

    // test-and-stage on a PRELOADED q value (no LDS inside)
    #define TESTQ(q, jj)                                                       \
        if ((q) != 0.0f) {                                                     \
            float v = (q) * __ldg(values + (jj));                              \
            int p = atomicAdd(&sc_cnt, 1);                                     \
            if (p < STAGE_CAP) { sc_pos[p] = (jj); sc_val[p] = v; }            \
            else {                                                             \
                int gp = atomicAdd(&g_novf, 1);                                \
                if (gp < OVF_CAP) {                                            \
                    g_ovf_pos[gp] = (jj); g_ovf_val[gp] = v;                   \
                }                                                              \
            }                                                                  \
        }

    // per-int4 group: 4 pipelined LDS, then 4 tests (register-light)
    #define GROUP4(t, jj)                                                      \
        {                                                                      \
            float q0 = qtab[(t).x];                                            \
            float q1 = qtab[(t).y];                                            \
            float q2 = qtab[(t).z];                                            \
            float q3 = qtab[(t).w];                                            \
            TESTQ(q0, (jj))     TESTQ(q1, (jj) + 1)                            \
            TESTQ(q2, (jj) + 2) TESTQ(q3, (jj) + 3)                            \
        }

    int i = gtid;
    for (; i + 3 * gsz < total4; i += 4 * gsz) {
        int4 a = __ldcs(ind4 + i);
        int4 b = __ldcs(ind4 + i + gsz);
        int4 c = __ldcs(ind4 + i + 2 * gsz);
        int4 d = __ldcs(ind4 + i + 3 * gsz);

        GROUP4(a, (i) << 2)
        GROUP4(b, (i + gsz) << 2)
        GROUP4(c, (i + 2 * gsz) << 2)
        GROUP4(d, (i + 3 * gsz) << 2)
    }
    for (; i < total4; i += gsz) {
        int4 a = __ldcs(ind4 + i);
        GROUP4(a, i << 2)
    }
    int jt = (total4 << 2) + gtid;
    if (jt < nnz) {
        float q = qtab[indice[jt]];
        TESTQ(q, jt)
    }
    #undef GROUP4
    #undef TESTQ

    // ---- per-CTA resolve of staged hits (parallel binary searches) ----
    __syncthreads();
    int nh = sc_cnt; if (nh > STAGE_CAP) nh = STAGE_CAP;
    for (int t = threadIdx.x; t < nh; t += 1024) {
        int j = sc_pos[t];
        int lo = 0, hi = n_docs;
        while (lo < hi) {
            int mid = (lo + hi + 1) >> 1;
            if (crow[mid] <= j) lo = mid; else hi = mid - 1;
        }
        float old = atomicAdd(&g_scores[lo], sc_val[t]);
        if (old == 0.0f) {
            int p = atomicAdd(&cd_cnt, 1);
            if (p < STAGE_CAP) cd_doc[p] = lo;
            else {
                int gp = atomicAdd(&g_ncand, 1);
                if (gp < CAND_CAP) g_cand_doc[gp] = lo;
            }
        }
    }

    // ---- flush candidates: ONE global atomic per CTA ----
    __syncthreads();
    if (threadIdx.x == 0) {
        int c = cd_cnt; if (c > STAGE_CAP) c = STAGE_CAP;
        int base = atomicAdd(&g_ncand, c);
        if (base + c > CAND_CAP) c = (base < CAND_CAP) ? (CAND_CAP - base) : 0;
        cd_base = base; cd_flush = c;
    }
    __syncthreads();
    for (int t = threadIdx.x; t < cd_flush; t += 1024)
        g_cand_doc[cd_base + t] = cd_doc[t];

    // ---- completion ticket: t0-only cumulative fence (release+acquire) ----
    __syncthreads();
    if (threadIdx.x == 0) {
        __threadfence();
        s_last = (atomicAdd(&g_done, 1) == gridDim.x - 1) ? 1 : 0;
        if (s_last) __threadfence();
    }
    __syncthreads();
    if (s_last) {
        int no = g_novf; if (no > OVF_CAP) no = OVF_CAP;
        for (int t = threadIdx.x; t < no; t += 1024) {
            int j = g_ovf_pos[t];
            int lo = 0, hi = n_docs;
            while (lo < hi) {
                int mid = (lo + hi + 1) >> 1;
                if (crow[mid] <= j) lo = mid; else hi = mid - 1;
            }
            float old = atomicAdd(&g_scores[lo], g_ovf_val[t]);
            if (old == 0.0f) {
                int gp = atomicAdd(&g_ncand, 1);
                if (gp < CAND_CAP) g_cand_doc[gp] = lo;
            }
        }
    }
}

// ---------------------------------------------------------------------------
// top-k helpers (static register indexing only)
// ---------------------------------------------------------------------------
__device__ __forceinline__ void insert10(float* lv, int* li, float s, int d) {
    if (s > lv[TOPK - 1] || (s == lv[TOPK - 1] && d < li[TOPK - 1])) {
        lv[TOPK - 1] = s; li[TOPK - 1] = d;
        #pragma unroll
        for (int k = TOPK - 1; k > 0; k--) {
            bool sw = (lv[k] > lv[k - 1]) ||
                      (lv[k] == lv[k - 1] && li[k] < li[k - 1]);
            if (sw) {
                float tv = lv[k]; lv[k] = lv[k - 1]; lv[k - 1] = tv;
                int   ti = li[k]; li[k] = li[k - 1]; li[k - 1] = ti;
            }
        }
    }
}

__device__ __forceinline__ void warp_merge10(float* lv, int* li,
                                             float* out_v, int* out_i) {
    int lane = threadIdx.x & 31;
    #pragma unroll
    for (int r = 0; r < TOPK; r++) {
        float bv = lv[0]; int bi = li[0]; int bl = lane;
        #pragma unroll
        for (int off = 16; off; off >>= 1) {
            float ov = __shfl_down_sync(0xffffffffu, bv, off);
            int   oi = __shfl_down_sync(0xffffffffu, bi, off);
            int   ol = __shfl_down_sync(0xffffffffu, bl, off);
            if (ov > bv || (ov == bv && oi < bi)) { bv = ov; bi = oi; bl = ol; }
        }
        bl = __shfl_sync(0xffffffffu, bl, 0);
        float wv = __shfl_sync(0xffffffffu, bv, 0);
        int   wi = __shfl_sync(0xffffffffu, bi, 0);
        if (lane == bl) {
            #pragma unroll
            for (int k = 0; k < TOPK - 1; k++) { lv[k] = lv[k + 1]; li[k] = li[k + 1]; }
            lv[TOPK - 1] = -FLT_MAX; li[TOPK - 1] = INT_MAX;
        }
        if (lane == 0) { out_v[r] = wv; out_i[r] = wi; }
    }
}

__device__ __forceinline__ void block_merge10(const float* sv, const int* si,
                                              int nwarp, float* out_v, int* out_i) {
    int lane = threadIdx.x & 31;
    float lv[TOPK]; int li[TOPK];
    #pragma unroll
    for (int k = 0; k < TOPK; k++) {
        if (lane < nwarp) { lv[k] = sv[lane * TOPK + k]; li[k] = si[lane * TOPK + k]; }
        else              { lv[k] = -FLT_MAX;            li[k] = INT_MAX;            }
    }
    warp_merge10(lv, li, out_v, out_i);
}

// ---------------------------------------------------------------------------
// top-k (single kernel): per-block candidate scan with fused cleanup, block
// winners to global; last-finishing block merges winners, writes output,
// resets counters. out layout: [TOPK values][TOPK indices-as-float]
// ---------------------------------------------------------------------------
__global__ void __launch_bounds__(256)
topk_kernel(float* __restrict__ out, int out_size) {
    __shared__ float sv[8 * TOPK];
    __shared__ int   si[8 * TOPK];
    __shared__ int   s_last;

    float lv[TOPK]; int li[TOPK];
    #pragma unroll
    for (int k = 0; k < TOPK; k++) { lv[k] = -FLT_MAX; li[k] = INT_MAX; }

    int nc = g_ncand;
    if (nc > CAND_CAP) nc = CAND_CAP;
    int gtid = blockIdx.x * blockDim.x + threadIdx.x;
    int gsz  = gridDim.x * blockDim.x;

    int t = gtid;
    for (; t + 3 * gsz < nc; t += 4 * gsz) {
        int d0 = g_cand_doc[t];
        int d1 = g_cand_doc[t + gsz];
        int d2 = g_cand_doc[t + 2 * gsz];
        int d3 = g_cand_doc[t + 3 * gsz];
        float s0 = g_scores[d0];
        float s1 = g_scores[d1];
        float s2 = g_scores[d2];
        float s3 = g_scores[d3];
        g_scores[d0] = 0.0f;
        g_scores[d1] = 0.0f;
        g_scores[d2] = 0.0f;
        g_scores[d3] = 0.0f;
        insert10(lv, li, s0, d0);
        insert10(lv, li, s1, d1);
        insert10(lv, li, s2, d2);
        insert10(lv, li, s3, d3);
    }
    for (; t < nc; t += gsz) {
        int d = g_cand_doc[t];
        float s = g_scores[d];
        g_scores[d] = 0.0f;
        insert10(lv, li, s, d);
    }

    int wid = threadIdx.x >> 5;
    warp_merge10(lv, li, sv + wid * TOPK, si + wid * TOPK);
    __syncthreads();
    if (wid == 0)
        block_merge10(sv, si, 8, g_blk_v + blockIdx.x * TOPK,
                      g_blk_i + blockIdx.x * TOPK);

    // ---- ticket: t0-only cumulative fence ----
    __syncthreads();
    if (threadIdx.x == 0) {
        __threadfence();
        s_last = (atomicAdd(&g_tk_done, 1) == gridDim.x - 1) ? 1 : 0;
        if (s_last) __threadfence();
    }
    __syncthreads();
    if (!s_last) return;

    const int NC = NB1 * TOPK;
    #pragma unroll
    for (int k = 0; k < TOPK; k++) { lv[k] = -FLT_MAX; li[k] = INT_MAX; }
    for (int p = threadIdx.x; p < NC; p += 256)
        insert10(lv, li, g_blk_v[p], g_blk_i[p]);

    __syncthreads();   // reuse sv/si
    warp_merge10(lv, li, sv + wid * TOPK, si + wid * TOPK);
    __syncthreads();
    __shared__ float fv[TOPK];
    __shared__ int   fi[TOPK];
    if (wid == 0) block_merge10(sv, si, 8, fv, fi);
    __syncthreads();

    if (threadIdx.x < TOPK) {
        int k = threadIdx.x;
        if (k < out_size) out[k] = fv[k];
        if (TOPK + k < out_size) out[TOPK + k] = (float)fi[k];
    }
    if (threadIdx.x == 0) {   // reset all counters for next graph replay
        g_ncand = 0;
        g_novf = 0;
        g_done = 0;
        g_tk_done = 0;
    }
}

// ---------------------------------------------------------------------------
// kernel_launch
// Inputs: q_indices(i32,32) q_values(f32,32) crow(i32,N+1) indice(i32,nnz)
//         values(f32,nnz) [top_k]
// ---------------------------------------------------------------------------
extern "C" void kernel_launch(void* const* d_in, const int* in_sizes, int n_in,
                              void* d_out, int out_size) {
    const int*   qidx   = (const int*)d_in[0];
    const float* qval   = (const float*)d_in[1];
    const int*   crow   = (const int*)d_in[2];
    const int*   indice = (const int*)d_in[3];
    const float* values = (const float*)d_in[4];

    int qn     = in_sizes[0];
    int n_docs = in_sizes[2] - 1;
    int nnz    = in_sizes[3];

    const int SMEM_Q = VOCAB * (int)sizeof(float);
    cudaFuncSetAttribute(score_kernel, cudaFuncAttributeMaxDynamicSharedMemorySize, SMEM_Q);

    score_kernel<<<148, 1024, SMEM_Q>>>(qidx, qval, qn, indice, values,
                                        crow, n_docs, nnz);
    topk_kernel<<<NB1, 256>>>((float*)d_out, out_size);
}

// round 16
// speedup vs baseline: 1.5228x; 1.4631x over previous
#include <cuda_runtime.h>
#include <cfloat>
#include <climits>

#define VOCAB 30522
#define QT_BYTES 30528      // qtab_u8 padded to /4
#define CAND_CAP (1 << 20)
#define OVF_CAP  (1 << 18)
#define TOPK 10
#define NB1 296
#define STAGE_CAP 2048

// ---- device scratch (BSS zero-init; every launch restores the invariant) ----
__device__ float g_scores[500000];
__device__ int   g_cand_doc[CAND_CAP];
__device__ int   g_ncand;          // reset by topk last block
__device__ int   g_ovf_pos[OVF_CAP];
__device__ float g_ovf_val[OVF_CAP];
__device__ int   g_novf;           // reset by topk last block
__device__ int   g_done;           // score CTA ticket, reset by topk last block
__device__ int   g_tk_done;        // topk block ticket, reset by topk last block
__device__ float g_blk_v[NB1 * TOPK];
__device__ int   g_blk_i[NB1 * TOPK];

// ---------------------------------------------------------------------------
// score_fused v2: u8 slot-index query table (30.5 KB, vs 122 KB f32) lets TWO
// 1024-thread CTAs co-reside per SM -> occupancy 50% -> 100%. Hot loop keeps
// the R13-proven inline shape: LDS.U8 -> ISETP -> rare branch (branch arm
// reads the real q value from a 33-float table, near-broadcast). 2x LDG
// batching under the 32-reg cap (__launch_bounds__(1024,2)); SM-wide MLP
// unchanged (64 warps x 2 vs 32 x 4). Duplicated query indices coalesced by
// warp-parallel owner-dedup. Staging/resolve/ticket identical to R13.
// ---------------------------------------------------------------------------
__global__ void __launch_bounds__(1024, 2)
score_kernel(const int* __restrict__ qidx, const float* __restrict__ qval, int qn,
             const int* __restrict__ indice, const float* __restrict__ values,
             const int* __restrict__ crow, int n_docs, int nnz)
{
    extern __shared__ unsigned char qtab_u8[];   // QT_BYTES
    __shared__ float s_qv[33];        // slot -> summed query value (slot 0 unused)
    __shared__ int   s_qi[32];
    __shared__ int   sc_cnt;
    __shared__ int   sc_pos[STAGE_CAP];
    __shared__ float sc_val[STAGE_CAP];
    __shared__ int   cd_cnt;
    __shared__ int   cd_doc[STAGE_CAP];
    __shared__ int   cd_base, cd_flush;
    __shared__ int   s_last;

    // zero table (as words) + init
    for (int i = threadIdx.x; i < QT_BYTES / 4; i += 1024)
        ((unsigned int*)qtab_u8)[i] = 0u;
    if (threadIdx.x < 33) s_qv[threadIdx.x] = 0.0f;
    if (threadIdx.x < 32) s_qi[threadIdx.x] = (threadIdx.x < qn) ? qidx[threadIdx.x]
                                                                 : (-1 - threadIdx.x);
    if (threadIdx.x == 0) { sc_cnt = 0; cd_cnt = 0; }
    __syncthreads();

    // duplicate-coalescing: owner = first occurrence; others add into owner slot
    if (threadIdx.x < qn) {
        int e = s_qi[threadIdx.x];
        int owner = threadIdx.x;
        for (int j = 0; j < threadIdx.x; j++)
            if (s_qi[j] == e) { owner = j; break; }
        atomicAdd(&s_qv[owner + 1], qval[threadIdx.x]);
        if (owner == threadIdx.x)
            qtab_u8[e] = (unsigned char)(threadIdx.x + 1);
    }
    __syncthreads();

    const int gtid = blockIdx.x * 1024 + threadIdx.x;
    const int gsz  = gridDim.x * 1024;
    const int total4 = nnz >> 2;
    const int4* __restrict__ ind4 = (const int4*)indice;

    // R13-shape test: inline LDS.U8, rare branch stages the hit
    #define TESTB(e, jj)                                                       \
        {                                                                      \
            unsigned char s = qtab_u8[e];                                      \
            if (s) {                                                           \
                float v = s_qv[s] * __ldg(values + (jj));                      \
                int p = atomicAdd(&sc_cnt, 1);                                 \
                if (p < STAGE_CAP) { sc_pos[p] = (jj); sc_val[p] = v; }        \
                else {                                                         \
                    int gp = atomicAdd(&g_novf, 1);                            \
                    if (gp < OVF_CAP) {                                        \
                        g_ovf_pos[gp] = (jj); g_ovf_val[gp] = v;               \
                    }                                                          \
                }                                                              \
            }                                                                  \
        }
    #define TESTB4(t, jj) TESTB((t).x, jj) TESTB((t).y, (jj) + 1) \
                          TESTB((t).z, (jj) + 2) TESTB((t).w, (jj) + 3)

    int i = gtid;
    // 2x batch (32-reg budget at 2 CTAs/SM)
    for (; i + gsz < total4; i += 2 * gsz) {
        int4 a = __ldcs(ind4 + i);
        int4 b = __ldcs(ind4 + i + gsz);
        TESTB4(a, (i) << 2)
        TESTB4(b, (i + gsz) << 2)
    }
    for (; i < total4; i += gsz) {
        int4 a = __ldcs(ind4 + i);
        TESTB4(a, i << 2)
    }
    int jt = (total4 << 2) + gtid;
    if (jt < nnz) {
        TESTB(indice[jt], jt)
    }
    #undef TESTB4
    #undef TESTB

    // ---- per-CTA resolve of staged hits (parallel binary searches) ----
    __syncthreads();
    int nh = sc_cnt; if (nh > STAGE_CAP) nh = STAGE_CAP;
    for (int t = threadIdx.x; t < nh; t += 1024) {
        int j = sc_pos[t];
        int lo = 0, hi = n_docs;
        while (lo < hi) {
            int mid = (lo + hi + 1) >> 1;
            if (crow[mid] <= j) lo = mid; else hi = mid - 1;
        }
        float old = atomicAdd(&g_scores[lo], sc_val[t]);
        if (old == 0.0f) {
            int p = atomicAdd(&cd_cnt, 1);
            if (p < STAGE_CAP) cd_doc[p] = lo;
            else {
                int gp = atomicAdd(&g_ncand, 1);
                if (gp < CAND_CAP) g_cand_doc[gp] = lo;
            }
        }
    }

    // ---- flush candidates: ONE global atomic per CTA ----
    __syncthreads();
    if (threadIdx.x == 0) {
        int c = cd_cnt; if (c > STAGE_CAP) c = STAGE_CAP;
        int base = atomicAdd(&g_ncand, c);
        if (base + c > CAND_CAP) c = (base < CAND_CAP) ? (CAND_CAP - base) : 0;
        cd_base = base; cd_flush = c;
    }
    __syncthreads();
    for (int t = threadIdx.x; t < cd_flush; t += 1024)
        g_cand_doc[cd_base + t] = cd_doc[t];

    // ---- completion ticket: t0-only cumulative fence (release+acquire) ----
    __syncthreads();
    if (threadIdx.x == 0) {
        __threadfence();
        s_last = (atomicAdd(&g_done, 1) == gridDim.x - 1) ? 1 : 0;
        if (s_last) __threadfence();
    }
    __syncthreads();
    if (s_last) {
        int no = g_novf; if (no > OVF_CAP) no = OVF_CAP;
        for (int t = threadIdx.x; t < no; t += 1024) {
            int j = g_ovf_pos[t];
            int lo = 0, hi = n_docs;
            while (lo < hi) {
                int mid = (lo + hi + 1) >> 1;
                if (crow[mid] <= j) lo = mid; else hi = mid - 1;
            }
            float old = atomicAdd(&g_scores[lo], g_ovf_val[t]);
            if (old == 0.0f) {
                int gp = atomicAdd(&g_ncand, 1);
                if (gp < CAND_CAP) g_cand_doc[gp] = lo;
            }
        }
    }
}

// ---------------------------------------------------------------------------
// top-k helpers (static register indexing only)
// ---------------------------------------------------------------------------
__device__ __forceinline__ void insert10(float* lv, int* li, float s, int d) {
    if (s > lv[TOPK - 1] || (s == lv[TOPK - 1] && d < li[TOPK - 1])) {
        lv[TOPK - 1] = s; li[TOPK - 1] = d;
        #pragma unroll
        for (int k = TOPK - 1; k > 0; k--) {
            bool sw = (lv[k] > lv[k - 1]) ||
                      (lv[k] == lv[k - 1] && li[k] < li[k - 1]);
            if (sw) {
                float tv = lv[k]; lv[k] = lv[k - 1]; lv[k - 1] = tv;
                int   ti = li[k]; li[k] = li[k - 1]; li[k - 1] = ti;
            }
        }
    }
}

__device__ __forceinline__ void warp_merge10(float* lv, int* li,
                                             float* out_v, int* out_i) {
    int lane = threadIdx.x & 31;
    #pragma unroll
    for (int r = 0; r < TOPK; r++) {
        float bv = lv[0]; int bi = li[0]; int bl = lane;
        #pragma unroll
        for (int off = 16; off; off >>= 1) {
            float ov = __shfl_down_sync(0xffffffffu, bv, off);
            int   oi = __shfl_down_sync(0xffffffffu, bi, off);
            int   ol = __shfl_down_sync(0xffffffffu, bl, off);
            if (ov > bv || (ov == bv && oi < bi)) { bv = ov; bi = oi; bl = ol; }
        }
        bl = __shfl_sync(0xffffffffu, bl, 0);
        float wv = __shfl_sync(0xffffffffu, bv, 0);
        int   wi = __shfl_sync(0xffffffffu, bi, 0);
        if (lane == bl) {
            #pragma unroll
            for (int k = 0; k < TOPK - 1; k++) { lv[k] = lv[k + 1]; li[k] = li[k + 1]; }
            lv[TOPK - 1] = -FLT_MAX; li[TOPK - 1] = INT_MAX;
        }
        if (lane == 0) { out_v[r] = wv; out_i[r] = wi; }
    }
}

__device__ __forceinline__ void block_merge10(const float* sv, const int* si,
                                              int nwarp, float* out_v, int* out_i) {
    int lane = threadIdx.x & 31;
    float lv[TOPK]; int li[TOPK];
    #pragma unroll
    for (int k = 0; k < TOPK; k++) {
        if (lane < nwarp) { lv[k] = sv[lane * TOPK + k]; li[k] = si[lane * TOPK + k]; }
        else              { lv[k] = -FLT_MAX;            li[k] = INT_MAX;            }
    }
    warp_merge10(lv, li, out_v, out_i);
}

// ---------------------------------------------------------------------------
// top-k (single kernel): per-block candidate scan with fused cleanup, block
// winners to global; last-finishing block merges winners, writes output,
// resets counters. out layout: [TOPK values][TOPK indices-as-float]
// ---------------------------------------------------------------------------
__global__ void __launch_bounds__(256)
topk_kernel(float* __restrict__ out, int out_size) {
    __shared__ float sv[8 * TOPK];
    __shared__ int   si[8 * TOPK];
    __shared__ int   s_last;

    float lv[TOPK]; int li[TOPK];
    #pragma unroll
    for (int k = 0; k < TOPK; k++) { lv[k] = -FLT_MAX; li[k] = INT_MAX; }

    int nc = g_ncand;
    if (nc > CAND_CAP) nc = CAND_CAP;
    int gtid = blockIdx.x * blockDim.x + threadIdx.x;
    int gsz  = gridDim.x * blockDim.x;

    int t = gtid;
    for (; t + 3 * gsz < nc; t += 4 * gsz) {
        int d0 = g_cand_doc[t];
        int d1 = g_cand_doc[t + gsz];
        int d2 = g_cand_doc[t + 2 * gsz];
        int d3 = g_cand_doc[t + 3 * gsz];
        float s0 = g_scores[d0];
        float s1 = g_scores[d1];
        float s2 = g_scores[d2];
        float s3 = g_scores[d3];
        g_scores[d0] = 0.0f;
        g_scores[d1] = 0.0f;
        g_scores[d2] = 0.0f;
        g_scores[d3] = 0.0f;
        insert10(lv, li, s0, d0);
        insert10(lv, li, s1, d1);
        insert10(lv, li, s2, d2);
        insert10(lv, li, s3, d3);
    }
    for (; t < nc; t += gsz) {
        int d = g_cand_doc[t];
        float s = g_scores[d];
        g_scores[d] = 0.0f;
        insert10(lv, li, s, d);
    }

    int wid = threadIdx.x >> 5;
    warp_merge10(lv, li, sv + wid * TOPK, si + wid * TOPK);
    __syncthreads();
    if (wid == 0)
        block_merge10(sv, si, 8, g_blk_v + blockIdx.x * TOPK,
                      g_blk_i + blockIdx.x * TOPK);

    // ---- ticket: t0-only cumulative fence ----
    __syncthreads();
    if (threadIdx.x == 0) {
        __threadfence();
        s_last = (atomicAdd(&g_tk_done, 1) == gridDim.x - 1) ? 1 : 0;
        if (s_last) __threadfence();
    }
    __syncthreads();
    if (!s_last) return;

    const int NC = NB1 * TOPK;
    #pragma unroll
    for (int k = 0; k < TOPK; k++) { lv[k] = -FLT_MAX; li[k] = INT_MAX; }
    for (int p = threadIdx.x; p < NC; p += 256)
        insert10(lv, li, g_blk_v[p], g_blk_i[p]);

    __syncthreads();   // reuse sv/si
    warp_merge10(lv, li, sv + wid * TOPK, si + wid * TOPK);
    __syncthreads();
    __shared__ float fv[TOPK];
    __shared__ int   fi[TOPK];
    if (wid == 0) block_merge10(sv, si, 8, fv, fi);
    __syncthreads();

    if (threadIdx.x < TOPK) {
        int k = threadIdx.x;
        if (k < out_size) out[k] = fv[k];
        if (TOPK + k < out_size) out[TOPK + k] = (float)fi[k];
    }
    if (threadIdx.x == 0) {   // reset all counters for next graph replay
        g_ncand = 0;
        g_novf = 0;
        g_done = 0;
        g_tk_done = 0;
    }
}

// ---------------------------------------------------------------------------
// kernel_launch
// Inputs: q_indices(i32,32) q_values(f32,32) crow(i32,N+1) indice(i32,nnz)
//         values(f32,nnz) [top_k]
// ---------------------------------------------------------------------------
extern "C" void kernel_launch(void* const* d_in, const int* in_sizes, int n_in,
                              void* d_out, int out_size) {
    const int*   qidx   = (const int*)d_in[0];
    const float* qval   = (const float*)d_in[1];
    const int*   crow   = (const int*)d_in[2];
    const int*   indice = (const int*)d_in[3];
    const float* values = (const float*)d_in[4];

    int qn     = in_sizes[0];
    int n_docs = in_sizes[2] - 1;
    int nnz    = in_sizes[3];

    cudaFuncSetAttribute(score_kernel, cudaFuncAttributeMaxDynamicSharedMemorySize, QT_BYTES);

    score_kernel<<<296, 1024, QT_BYTES>>>(qidx, qval, qn, indice, values,
                                          crow, n_docs, nnz);
    topk_kernel<<<NB1, 256>>>((float*)d_out, out_size);
}

// round 17
// speedup vs baseline: 1.5326x; 1.0065x over previous
#include <cuda_runtime.h>
#include <cfloat>
#include <climits>

#define VOCAB 30522
#define QT_BYTES 30528      // qtab_u8 padded to /4
#define CAND_CAP (1 << 20)
#define OVF_CAP  (1 << 18)
#define TOPK 10
#define NB1 148             // topk blocks (1024 thr each, one wave)
#define STAGE_CAP 2048

// ---- device scratch (BSS zero-init; every launch restores the invariant) ----
__device__ float g_scores[500000];
__device__ int   g_cand_doc[CAND_CAP];
__device__ int   g_ncand;          // reset by topk last block
__device__ int   g_ovf_pos[OVF_CAP];
__device__ float g_ovf_val[OVF_CAP];
__device__ int   g_novf;           // reset by topk last block
__device__ int   g_done;           // score CTA ticket, reset by topk last block
__device__ int   g_tk_done;        // topk block ticket, reset by topk last block
__device__ float g_blk_v[NB1 * TOPK];
__device__ int   g_blk_i[NB1 * TOPK];

// ---------------------------------------------------------------------------
// score_fused (FROZEN since R16 win): u8 slot-index query table (30.5 KB)
// -> 2 CTAs/SM -> 64 resident warps. Hot loop: LDS.U8 -> ISETP -> rare
// branch; 2x LDG batch under the 32-reg cap. CTA staging + per-CTA resolve;
// t0-only cumulative fences.
// ---------------------------------------------------------------------------
__global__ void __launch_bounds__(1024, 2)
score_kernel(const int* __restrict__ qidx, const float* __restrict__ qval, int qn,
             const int* __restrict__ indice, const float* __restrict__ values,
             const int* __restrict__ crow, int n_docs, int nnz)
{
    extern __shared__ unsigned char qtab_u8[];   // QT_BYTES
    __shared__ float s_qv[33];        // slot -> summed query value (slot 0 unused)
    __shared__ int   s_qi[32];
    __shared__ int   sc_cnt;
    __shared__ int   sc_pos[STAGE_CAP];
    __shared__ float sc_val[STAGE_CAP];
    __shared__ int   cd_cnt;
    __shared__ int   cd_doc[STAGE_CAP];
    __shared__ int   cd_base, cd_flush;
    __shared__ int   s_last;

    for (int i = threadIdx.x; i < QT_BYTES / 4; i += 1024)
        ((unsigned int*)qtab_u8)[i] = 0u;
    if (threadIdx.x < 33) s_qv[threadIdx.x] = 0.0f;
    if (threadIdx.x < 32) s_qi[threadIdx.x] = (threadIdx.x < qn) ? qidx[threadIdx.x]
                                                                 : (-1 - threadIdx.x);
    if (threadIdx.x == 0) { sc_cnt = 0; cd_cnt = 0; }
    __syncthreads();

    // duplicate-coalescing: owner = first occurrence; others add into owner slot
    if (threadIdx.x < qn) {
        int e = s_qi[threadIdx.x];
        int owner = threadIdx.x;
        for (int j = 0; j < threadIdx.x; j++)
            if (s_qi[j] == e) { owner = j; break; }
        atomicAdd(&s_qv[owner + 1], qval[threadIdx.x]);
        if (owner == threadIdx.x)
            qtab_u8[e] = (unsigned char)(threadIdx.x + 1);
    }
    __syncthreads();

    const int gtid = blockIdx.x * 1024 + threadIdx.x;
    const int gsz  = gridDim.x * 1024;
    const int total4 = nnz >> 2;
    const int4* __restrict__ ind4 = (const int4*)indice;

    #define TESTB(e, jj)                                                       \
        {                                                                      \
            unsigned char s = qtab_u8[e];                                      \
            if (s) {                                                           \
                float v = s_qv[s] * __ldg(values + (jj));                      \
                int p = atomicAdd(&sc_cnt, 1);                                 \
                if (p < STAGE_CAP) { sc_pos[p] = (jj); sc_val[p] = v; }        \
                else {                                                         \
                    int gp = atomicAdd(&g_novf, 1);                            \
                    if (gp < OVF_CAP) {                                        \
                        g_ovf_pos[gp] = (jj); g_ovf_val[gp] = v;               \
                    }                                                          \
                }                                                              \
            }                                                                  \
        }
    #define TESTB4(t, jj) TESTB((t).x, jj) TESTB((t).y, (jj) + 1) \
                          TESTB((t).z, (jj) + 2) TESTB((t).w, (jj) + 3)

    int i = gtid;
    for (; i + gsz < total4; i += 2 * gsz) {
        int4 a = __ldcs(ind4 + i);
        int4 b = __ldcs(ind4 + i + gsz);
        TESTB4(a, (i) << 2)
        TESTB4(b, (i + gsz) << 2)
    }
    for (; i < total4; i += gsz) {
        int4 a = __ldcs(ind4 + i);
        TESTB4(a, i << 2)
    }
    int jt = (total4 << 2) + gtid;
    if (jt < nnz) {
        TESTB(indice[jt], jt)
    }
    #undef TESTB4
    #undef TESTB

    // ---- per-CTA resolve of staged hits (parallel binary searches) ----
    __syncthreads();
    int nh = sc_cnt; if (nh > STAGE_CAP) nh = STAGE_CAP;
    for (int t = threadIdx.x; t < nh; t += 1024) {
        int j = sc_pos[t];
        int lo = 0, hi = n_docs;
        while (lo < hi) {
            int mid = (lo + hi + 1) >> 1;
            if (crow[mid] <= j) lo = mid; else hi = mid - 1;
        }
        float old = atomicAdd(&g_scores[lo], sc_val[t]);
        if (old == 0.0f) {
            int p = atomicAdd(&cd_cnt, 1);
            if (p < STAGE_CAP) cd_doc[p] = lo;
            else {
                int gp = atomicAdd(&g_ncand, 1);
                if (gp < CAND_CAP) g_cand_doc[gp] = lo;
            }
        }
    }

    // ---- flush candidates: ONE global atomic per CTA ----
    __syncthreads();
    if (threadIdx.x == 0) {
        int c = cd_cnt; if (c > STAGE_CAP) c = STAGE_CAP;
        int base = atomicAdd(&g_ncand, c);
        if (base + c > CAND_CAP) c = (base < CAND_CAP) ? (CAND_CAP - base) : 0;
        cd_base = base; cd_flush = c;
    }
    __syncthreads();
    for (int t = threadIdx.x; t < cd_flush; t += 1024)
        g_cand_doc[cd_base + t] = cd_doc[t];

    // ---- completion ticket: t0-only cumulative fence (release+acquire) ----
    __syncthreads();
    if (threadIdx.x == 0) {
        __threadfence();
        s_last = (atomicAdd(&g_done, 1) == gridDim.x - 1) ? 1 : 0;
        if (s_last) __threadfence();
    }
    __syncthreads();
    if (s_last) {
        int no = g_novf; if (no > OVF_CAP) no = OVF_CAP;
        for (int t = threadIdx.x; t < no; t += 1024) {
            int j = g_ovf_pos[t];
            int lo = 0, hi = n_docs;
            while (lo < hi) {
                int mid = (lo + hi + 1) >> 1;
                if (crow[mid] <= j) lo = mid; else hi = mid - 1;
            }
            float old = atomicAdd(&g_scores[lo], g_ovf_val[t]);
            if (old == 0.0f) {
                int gp = atomicAdd(&g_ncand, 1);
                if (gp < CAND_CAP) g_cand_doc[gp] = lo;
            }
        }
    }
}

// ---------------------------------------------------------------------------
// top-k helpers (static register indexing only)
// ---------------------------------------------------------------------------
__device__ __forceinline__ void insert10(float* lv, int* li, float s, int d) {
    if (s > lv[TOPK - 1] || (s == lv[TOPK - 1] && d < li[TOPK - 1])) {
        lv[TOPK - 1] = s; li[TOPK - 1] = d;
        #pragma unroll
        for (int k = TOPK - 1; k > 0; k--) {
            bool sw = (lv[k] > lv[k - 1]) ||
                      (lv[k] == lv[k - 1] && li[k] < li[k - 1]);
            if (sw) {
                float tv = lv[k]; lv[k] = lv[k - 1]; lv[k - 1] = tv;
                int   ti = li[k]; li[k] = li[k - 1]; li[k - 1] = ti;
            }
        }
    }
}

__device__ __forceinline__ void warp_merge10(float* lv, int* li,
                                             float* out_v, int* out_i) {
    int lane = threadIdx.x & 31;
    #pragma unroll
    for (int r = 0; r < TOPK; r++) {
        float bv = lv[0]; int bi = li[0]; int bl = lane;
        #pragma unroll
        for (int off = 16; off; off >>= 1) {
            float ov = __shfl_down_sync(0xffffffffu, bv, off);
            int   oi = __shfl_down_sync(0xffffffffu, bi, off);
            int   ol = __shfl_down_sync(0xffffffffu, bl, off);
            if (ov > bv || (ov == bv && oi < bi)) { bv = ov; bi = oi; bl = ol; }
        }
        bl = __shfl_sync(0xffffffffu, bl, 0);
        float wv = __shfl_sync(0xffffffffu, bv, 0);
        int   wi = __shfl_sync(0xffffffffu, bi, 0);
        if (lane == bl) {
            #pragma unroll
            for (int k = 0; k < TOPK - 1; k++) { lv[k] = lv[k + 1]; li[k] = li[k + 1]; }
            lv[TOPK - 1] = -FLT_MAX; li[TOPK - 1] = INT_MAX;
        }
        if (lane == 0) { out_v[r] = wv; out_i[r] = wi; }
    }
}

// one warp merges nwarp (<=32) sorted 10-lists from smem -> out[0..9]
__device__ __forceinline__ void block_merge10(const float* sv, const int* si,
                                              int nwarp, float* out_v, int* out_i) {
    int lane = threadIdx.x & 31;
    float lv[TOPK]; int li[TOPK];
    #pragma unroll
    for (int k = 0; k < TOPK; k++) {
        if (lane < nwarp) { lv[k] = sv[lane * TOPK + k]; li[k] = si[lane * TOPK + k]; }
        else              { lv[k] = -FLT_MAX;            li[k] = INT_MAX;            }
    }
    warp_merge10(lv, li, out_v, out_i);
}

// ---------------------------------------------------------------------------
// top-k (single kernel, 148 x 1024): candidate scan with fused cleanup;
// 32-warp two-level merge per block (same 10 shuffle rounds as 8-warp);
// last-finishing block merges the 148 winner lists, writes output, resets
// counters. out layout: [TOPK values][TOPK indices-as-float]
// ---------------------------------------------------------------------------
__global__ void __launch_bounds__(1024)
topk_kernel(float* __restrict__ out, int out_size) {
    __shared__ float sv[32 * TOPK];
    __shared__ int   si[32 * TOPK];
    __shared__ int   s_last;

    float lv[TOPK]; int li[TOPK];
    #pragma unroll
    for (int k = 0; k < TOPK; k++) { lv[k] = -FLT_MAX; li[k] = INT_MAX; }

    int nc = g_ncand;
    if (nc > CAND_CAP) nc = CAND_CAP;
    int gtid = blockIdx.x * blockDim.x + threadIdx.x;
    int gsz  = gridDim.x * blockDim.x;

    int t = gtid;
    for (; t + 3 * gsz < nc; t += 4 * gsz) {
        int d0 = g_cand_doc[t];
        int d1 = g_cand_doc[t + gsz];
        int d2 = g_cand_doc[t + 2 * gsz];
        int d3 = g_cand_doc[t + 3 * gsz];
        float s0 = g_scores[d0];
        float s1 = g_scores[d1];
        float s2 = g_scores[d2];
        float s3 = g_scores[d3];
        g_scores[d0] = 0.0f;
        g_scores[d1] = 0.0f;
        g_scores[d2] = 0.0f;
        g_scores[d3] = 0.0f;
        insert10(lv, li, s0, d0);
        insert10(lv, li, s1, d1);
        insert10(lv, li, s2, d2);
        insert10(lv, li, s3, d3);
    }
    for (; t < nc; t += gsz) {
        int d = g_cand_doc[t];
        float s = g_scores[d];
        g_scores[d] = 0.0f;
        insert10(lv, li, s, d);
    }

    int wid = threadIdx.x >> 5;
    warp_merge10(lv, li, sv + wid * TOPK, si + wid * TOPK);
    __syncthreads();
    if (wid == 0)
        block_merge10(sv, si, 32, g_blk_v + blockIdx.x * TOPK,
                      g_blk_i + blockIdx.x * TOPK);

    // ---- ticket: t0-only cumulative fence ----
    __syncthreads();
    if (threadIdx.x == 0) {
        __threadfence();
        s_last = (atomicAdd(&g_tk_done, 1) == gridDim.x - 1) ? 1 : 0;
        if (s_last) __threadfence();
    }
    __syncthreads();
    if (!s_last) return;

    // final merge of NB1 winner lists (1480 entries) by the last block
    const int NC = NB1 * TOPK;
    #pragma unroll
    for (int k = 0; k < TOPK; k++) { lv[k] = -FLT_MAX; li[k] = INT_MAX; }
    for (int p = threadIdx.x; p < NC; p += 1024)
        insert10(lv, li, g_blk_v[p], g_blk_i[p]);

    __syncthreads();   // reuse sv/si
    warp_merge10(lv, li, sv + wid * TOPK, si + wid * TOPK);
    __syncthreads();
    __shared__ float fv[TOPK];
    __shared__ int   fi[TOPK];
    if (wid == 0) block_merge10(sv, si, 32, fv, fi);
    __syncthreads();

    if (threadIdx.x < TOPK) {
        int k = threadIdx.x;
        if (k < out_size) out[k] = fv[k];
        if (TOPK + k < out_size) out[TOPK + k] = (float)fi[k];
    }
    if (threadIdx.x == 0) {   // reset all counters for next graph replay
        g_ncand = 0;
        g_novf = 0;
        g_done = 0;
        g_tk_done = 0;
    }
}

// ---------------------------------------------------------------------------
// kernel_launch
// Inputs: q_indices(i32,32) q_values(f32,32) crow(i32,N+1) indice(i32,nnz)
//         values(f32,nnz) [top_k]
// ---------------------------------------------------------------------------
extern "C" void kernel_launch(void* const* d_in, const int* in_sizes, int n_in,
                              void* d_out, int out_size) {
    const int*   qidx   = (const int*)d_in[0];
    const float* qval   = (const float*)d_in[1];
    const int*   crow   = (const int*)d_in[2];
    const int*   indice = (const int*)d_in[3];
    const float* values = (const float*)d_in[4];

    int qn     = in_sizes[0];
    int n_docs = in_sizes[2] - 1;
    int nnz    = in_sizes[3];

    cudaFuncSetAttribute(score_kernel, cudaFuncAttributeMaxDynamicSharedMemorySize, QT_BYTES);

    score_kernel<<<296, 1024, QT_BYTES>>>(qidx, qval, qn, indice, values,
                                          crow, n_docs, nnz);
    topk_kernel<<<NB1, 1024>>>((float*)d_out, out_size);
}